// round 5
// baseline (speedup 1.0000x reference)
#include <cuda_runtime.h>
#include <cuda_bf16.h>
#include <cstdint>
#include <math.h>

#define N_NODES 100000
#define N_EDGES 1600000
#define IN_F    512
#define HID     16
#define NCLS    7

// ---------------- scratch (static device globals; no runtime allocation) ----
__device__ float4 g_h1v[N_NODES * 4];      // X@W1, 16 floats/node   (6.4 MB)
__device__ float  g_h2[N_NODES * 8];       // layer-2 features, padded to 8
__device__ float  g_dinv[N_NODES];         // D^-1/2
__device__ int    g_cnt[N_NODES];          // in-degree (excl. self loop)
__device__ int    g_rowptr[N_NODES];       // CSR row starts (by dst)
__device__ int    g_rowfill[N_NODES];      // scatter cursors
__device__ int2   g_edges[N_EDGES];        // {src, bitcast(norm)} grouped by dst
__device__ int    g_is64;                  // edge_index dtype flag

// ---------------- dtype detect ----------------------------------------------
// int64 layout: words [0, 2E) are {lo,hi} pairs of src; hi words all 0.
// int32 layout: words [0, 2E) are src then dst values; odd words ~never all 0.
// Only reads words < 2*N_EDGES, safe under BOTH interpretations.
__global__ void k_detect(const int* __restrict__ ei32) {
    __shared__ int found;
    if (threadIdx.x == 0) found = 0;
    __syncthreads();
    for (int k = threadIdx.x; k < 4096; k += 256) {
        long long idx = (1LL + (long long)k * 781LL) | 1LL;   // odd words
        if (idx < 2LL * N_EDGES && ei32[idx] != 0) found = 1;
    }
    __syncthreads();
    if (threadIdx.x == 0) g_is64 = (found == 0);
}

// ---------------- CSR construction ------------------------------------------
__global__ void __launch_bounds__(256) k_zero_cnt() {
    int i = blockIdx.x * blockDim.x + threadIdx.x;
    if (i < N_NODES) g_cnt[i] = 0;
}

__global__ void __launch_bounds__(256) k_hist(const int* __restrict__ ei32) {
    int i = blockIdx.x * blockDim.x + threadIdx.x;
    if (i < N_EDGES) {
        int d = g_is64 ? ei32[2LL * N_EDGES + 2LL * i] : ei32[N_EDGES + i];
        if ((unsigned)d < N_NODES) atomicAdd(&g_cnt[d], 1);
    }
}

__global__ void __launch_bounds__(256) k_dinv() {
    int i = blockIdx.x * blockDim.x + threadIdx.x;
    if (i < N_NODES) g_dinv[i] = rsqrtf((float)(g_cnt[i] + 1));  // +1 self loop
}

// single-block exclusive scan of g_cnt -> g_rowptr / g_rowfill
__global__ void __launch_bounds__(1024) k_scan() {
    __shared__ int sh_warp[32];
    __shared__ int sh_carry;
    int tid = threadIdx.x, lane = tid & 31, wid = tid >> 5;
    if (tid == 0) sh_carry = 0;
    __syncthreads();
    for (int base = 0; base < N_NODES; base += 1024) {
        int i = base + tid;
        int v = (i < N_NODES) ? g_cnt[i] : 0;
        int x = v;
        #pragma unroll
        for (int d = 1; d < 32; d <<= 1) {
            int t = __shfl_up_sync(0xffffffffu, x, d);
            if (lane >= d) x += t;
        }
        if (lane == 31) sh_warp[wid] = x;
        __syncthreads();
        if (wid == 0) {
            int w = sh_warp[lane];
            #pragma unroll
            for (int d = 1; d < 32; d <<= 1) {
                int t = __shfl_up_sync(0xffffffffu, w, d);
                if (lane >= d) w += t;
            }
            sh_warp[lane] = w;
        }
        __syncthreads();
        int off = sh_carry + (wid > 0 ? sh_warp[wid - 1] : 0);
        if (i < N_NODES) {
            int excl = off + x - v;
            g_rowptr[i]  = excl;
            g_rowfill[i] = excl;
        }
        __syncthreads();
        if (tid == 0) sh_carry += sh_warp[31];
        __syncthreads();
    }
}

__global__ void __launch_bounds__(256) k_scatter(const int* __restrict__ ei32) {
    int i = blockIdx.x * blockDim.x + threadIdx.x;
    if (i < N_EDGES) {
        int s, d;
        if (g_is64) {
            s = ei32[2LL * i];
            d = ei32[2LL * N_EDGES + 2LL * i];
        } else {
            s = ei32[i];
            d = ei32[N_EDGES + i];
        }
        if ((unsigned)s < N_NODES && (unsigned)d < N_NODES) {
            int pos = atomicAdd(&g_rowfill[d], 1);
            if ((unsigned)pos < N_EDGES) {
                float w = g_dinv[s] * g_dinv[d];
                g_edges[pos] = make_int2(s, __float_as_int(w));
            }
        }
    }
}

// ---------------- GEMM1: h1 = X @ W1 (100k x 512 @ 512 x 16) ----------------
__global__ void __launch_bounds__(128) k_gemm1(const float* __restrict__ x,
                                               const float* __restrict__ W1) {
    __shared__ float  xs[128 * 65];    // scalar access only; pad avoids conflicts
    __shared__ float4 ws4[64 * 4];     // W chunk 64x16, float4-typed (aligned)
    int tid  = threadIdx.x;
    int row0 = blockIdx.x * 128;
    int rows = min(128, N_NODES - row0);

    float acc[HID];
    #pragma unroll
    for (int j = 0; j < HID; j++) acc[j] = 0.f;

    for (int c = 0; c < IN_F / 64; c++) {
        {
            const float4* Wv = (const float4*)(W1 + c * 64 * HID);
            for (int idx = tid; idx < 256; idx += 128) ws4[idx] = Wv[idx];
        }
        for (int idx = tid; idx < rows * 16; idx += 128) {
            int r = idx >> 4, k4 = (idx & 15) * 4;
            float4 v = *(const float4*)(x + (size_t)(row0 + r) * IN_F + c * 64 + k4);
            int b = r * 65 + k4;
            xs[b] = v.x; xs[b + 1] = v.y; xs[b + 2] = v.z; xs[b + 3] = v.w;
        }
        __syncthreads();
        if (tid < rows) {
            #pragma unroll 16
            for (int k = 0; k < 64; k++) {
                float xv = xs[tid * 65 + k];
                float4 w0 = ws4[k * 4 + 0], w1 = ws4[k * 4 + 1];
                float4 w2 = ws4[k * 4 + 2], w3 = ws4[k * 4 + 3];
                acc[0]  += xv * w0.x; acc[1]  += xv * w0.y; acc[2]  += xv * w0.z; acc[3]  += xv * w0.w;
                acc[4]  += xv * w1.x; acc[5]  += xv * w1.y; acc[6]  += xv * w1.z; acc[7]  += xv * w1.w;
                acc[8]  += xv * w2.x; acc[9]  += xv * w2.y; acc[10] += xv * w2.z; acc[11] += xv * w2.w;
                acc[12] += xv * w3.x; acc[13] += xv * w3.y; acc[14] += xv * w3.z; acc[15] += xv * w3.w;
            }
        }
        __syncthreads();
    }
    if (tid < rows) {
        int r = row0 + tid;
        g_h1v[r * 4 + 0] = make_float4(acc[0],  acc[1],  acc[2],  acc[3]);
        g_h1v[r * 4 + 1] = make_float4(acc[4],  acc[5],  acc[6],  acc[7]);
        g_h1v[r * 4 + 2] = make_float4(acc[8],  acc[9],  acc[10], acc[11]);
        g_h1v[r * 4 + 3] = make_float4(acc[12], acc[13], acc[14], acc[15]);
    }
}

// ---------------- agg layer 1 + bias + relu + GEMM2 fused -------------------
// warp per node: lanes split into 2 half-warps x 16 features, 2 edges/iter.
__global__ void __launch_bounds__(256) k_agg1(const float* __restrict__ b1,
                                              const float* __restrict__ W2) {
    __shared__ float W2s[HID * 8];   // padded cols, col 7 = 0
    __shared__ float b1s[HID];
    int tid = threadIdx.x;
    if (tid < 128) {
        int f = tid >> 3, j = tid & 7;
        W2s[tid] = (j < NCLS) ? W2[f * NCLS + j] : 0.f;
    }
    if (tid < HID) b1s[tid] = b1[tid];
    __syncthreads();

    const float* h1 = (const float*)g_h1v;
    int warp = tid >> 5, lane = tid & 31;
    int node = blockIdx.x * 8 + warp;
    if (node >= N_NODES) return;

    int start = g_rowptr[node];
    int cnt   = g_cnt[node];
    int f = lane & 15, half = lane >> 4;

    float acc = 0.f;
    for (int e = start + half; e < start + cnt; e += 2) {
        int2 ed = g_edges[e];
        unsigned s = (unsigned)ed.x;
        if (s < N_NODES) acc += h1[(size_t)s * HID + f] * __int_as_float(ed.y);
    }
    acc += __shfl_xor_sync(0xffffffffu, acc, 16);

    float di = g_dinv[node];
    acc += h1[(size_t)node * HID + f] * di * di;
    acc = fmaxf(acc + b1s[f], 0.f);

    // GEMM2: h2[j] = sum_f acc_f * W2[f][j]
    float hj = 0.f;
    #pragma unroll
    for (int ff = 0; ff < HID; ff++) {
        float a = __shfl_sync(0xffffffffu, acc, ff);
        hj += a * W2s[ff * 8 + (lane & 7)];
    }
    if (lane < 8) g_h2[(size_t)node * 8 + lane] = hj;   // lane 7 writes 0 pad
}

// ---------------- agg layer 2 + bias + log_softmax --------------------------
__global__ void __launch_bounds__(256) k_agg2(const float* __restrict__ b2,
                                              float* __restrict__ out) {
    __shared__ float b2s[8];
    int tid = threadIdx.x;
    if (tid < 8) b2s[tid] = (tid < NCLS) ? b2[tid] : 0.f;
    __syncthreads();

    int warp = tid >> 5, lane = tid & 31;
    int node = blockIdx.x * 8 + warp;
    if (node >= N_NODES) return;

    int start = g_rowptr[node];
    int cnt   = g_cnt[node];
    int j = lane & 7, q = lane >> 3;

    float acc = 0.f;
    for (int e = start + q; e < start + cnt; e += 4) {
        int2 ed = g_edges[e];
        unsigned s = (unsigned)ed.x;
        if (s < N_NODES) acc += g_h2[(size_t)s * 8 + j] * __int_as_float(ed.y);
    }
    acc += __shfl_xor_sync(0xffffffffu, acc, 16);
    acc += __shfl_xor_sync(0xffffffffu, acc, 8);

    float di = g_dinv[node];
    acc += g_h2[(size_t)node * 8 + j] * di * di + b2s[j];

    float v = (j < NCLS) ? acc : -1e30f;
    float m = v;
    m = fmaxf(m, __shfl_xor_sync(0xffffffffu, m, 4));
    m = fmaxf(m, __shfl_xor_sync(0xffffffffu, m, 2));
    m = fmaxf(m, __shfl_xor_sync(0xffffffffu, m, 1));
    float ex = (j < NCLS) ? expf(v - m) : 0.f;
    float s = ex;
    s += __shfl_xor_sync(0xffffffffu, s, 4);
    s += __shfl_xor_sync(0xffffffffu, s, 2);
    s += __shfl_xor_sync(0xffffffffu, s, 1);
    if (j < NCLS) out[(size_t)node * NCLS + j] = v - m - logf(s);
}

// ---------------- launch ----------------------------------------------------
// Inputs identified by ELEMENT COUNT (order-independent):
//   x: 51,200,000   edge_index: 3,200,000   W1: 8,192   b1: 16   W2: 112   b2: 7
extern "C" void kernel_launch(void* const* d_in, const int* in_sizes, int n_in,
                              void* d_out, int out_size) {
    const float* x  = nullptr;
    const int*   ei = nullptr;     // int32 view; dtype auto-detected on device
    const float* W1 = nullptr;
    const float* b1 = nullptr;
    const float* W2 = nullptr;
    const float* b2 = nullptr;

    for (int i = 0; i < n_in; i++) {
        long long sz = in_sizes[i];
        if      (sz == (long long)N_NODES * IN_F)                 x  = (const float*)d_in[i];
        else if (sz == 2LL * N_EDGES || sz == 4LL * N_EDGES)      ei = (const int*)d_in[i];
        else if (sz == (long long)IN_F * HID)                     W1 = (const float*)d_in[i];
        else if (sz == HID)                                       b1 = (const float*)d_in[i];
        else if (sz == (long long)HID * NCLS)                     W2 = (const float*)d_in[i];
        else if (sz == NCLS)                                      b2 = (const float*)d_in[i];
    }
    if (!x || !ei || !W1 || !b1 || !W2 || !b2) return;  // out stays poisoned -> visible failure
    float* out = (float*)d_out;

    k_detect<<<1, 256>>>(ei);
    k_zero_cnt<<<(N_NODES + 255) / 256, 256>>>();
    k_hist<<<(N_EDGES + 255) / 256, 256>>>(ei);
    k_dinv<<<(N_NODES + 255) / 256, 256>>>();
    k_scan<<<1, 1024>>>();
    k_scatter<<<(N_EDGES + 255) / 256, 256>>>(ei);
    k_gemm1<<<(N_NODES + 127) / 128, 128>>>(x, W1);
    k_agg1<<<(N_NODES + 7) / 8, 256>>>(b1, W2);
    k_agg2<<<(N_NODES + 7) / 8, 256>>>(b2, out);
}

// round 6
// speedup vs baseline: 1.3190x; 1.3190x over previous
#include <cuda_runtime.h>
#include <cuda_bf16.h>
#include <cstdint>
#include <math.h>

#define N_NODES 100000
#define N_EDGES 1600000
#define IN_F    512
#define HID     16
#define NCLS    7
#define NB      98          // ceil(N_NODES / 1024)

// ---------------- scratch (static device globals; no runtime allocation) ----
__device__ float4 g_h1v[N_NODES * 4];      // X@W1, 16 floats/node   (6.4 MB)
__device__ float  g_h2[N_NODES * 8];       // layer-2 features, padded to 8
__device__ float  g_dinv[N_NODES];         // D^-1/2
__device__ int    g_cnt[N_NODES];          // in-degree (excl. self loop)
__device__ int    g_rowptr[N_NODES];       // CSR row starts (by dst)
__device__ int    g_rowfill[N_NODES];      // scatter cursors
__device__ int2   g_edges[N_EDGES];        // {src, bitcast(norm)} grouped by dst
__device__ int    g_is64;                  // edge_index dtype flag
__device__ int    g_bsum[128];             // per-block cnt sums
__device__ int    g_boff[128];             // per-block exclusive offsets

// ---------------- f32x2 helpers (Blackwell packed fp32) ---------------------
__device__ __forceinline__ unsigned long long fma2(unsigned long long a,
                                                   unsigned long long b,
                                                   unsigned long long c) {
    unsigned long long d;
    asm("fma.rn.f32x2 %0, %1, %2, %3;" : "=l"(d) : "l"(a), "l"(b), "l"(c));
    return d;
}
__device__ __forceinline__ unsigned long long bcast2(float v) {
    unsigned long long d;
    asm("mov.b64 %0, {%1, %1};" : "=l"(d) : "f"(v));
    return d;
}
__device__ __forceinline__ float2 unpack2(unsigned long long v) {
    float2 r;
    asm("mov.b64 {%0, %1}, %2;" : "=f"(r.x), "=f"(r.y) : "l"(v));
    return r;
}

// ---------------- dtype detect ----------------------------------------------
__global__ void k_detect(const int* __restrict__ ei32) {
    __shared__ int found;
    if (threadIdx.x == 0) found = 0;
    __syncthreads();
    for (int k = threadIdx.x; k < 4096; k += 256) {
        long long idx = (1LL + (long long)k * 781LL) | 1LL;   // odd words
        if (idx < 2LL * N_EDGES && ei32[idx] != 0) found = 1;
    }
    __syncthreads();
    if (threadIdx.x == 0) g_is64 = (found == 0);
}

// ---------------- CSR construction ------------------------------------------
__global__ void __launch_bounds__(256) k_zero_cnt() {
    int i = blockIdx.x * blockDim.x + threadIdx.x;
    if (i < N_NODES) g_cnt[i] = 0;
}

__global__ void __launch_bounds__(256) k_hist(const int* __restrict__ ei32) {
    int i = blockIdx.x * blockDim.x + threadIdx.x;
    if (i < N_EDGES) {
        int d = g_is64 ? ei32[2LL * N_EDGES + 2LL * i] : ei32[N_EDGES + i];
        if ((unsigned)d < N_NODES) atomicAdd(&g_cnt[d], 1);
    }
}

// scan phase A: per-block sums of g_cnt (+ fused dinv)
__global__ void __launch_bounds__(1024) k_scanA() {
    __shared__ int sh[32];
    int t = threadIdx.x, lane = t & 31, wid = t >> 5;
    long long i = (long long)blockIdx.x * 1024 + t;
    int v = (i < N_NODES) ? g_cnt[i] : 0;
    if (i < N_NODES) g_dinv[i] = rsqrtf((float)(v + 1));
    int s = v;
    #pragma unroll
    for (int d = 16; d > 0; d >>= 1) s += __shfl_xor_sync(0xffffffffu, s, d);
    if (lane == 0) sh[wid] = s;
    __syncthreads();
    if (wid == 0) {
        int w = sh[lane];
        #pragma unroll
        for (int d = 16; d > 0; d >>= 1) w += __shfl_xor_sync(0xffffffffu, w, d);
        if (lane == 0) g_bsum[blockIdx.x] = w;
    }
}

// scan phase B: exclusive scan of NB block sums (single block, 128 threads)
__global__ void __launch_bounds__(128) k_scanB() {
    __shared__ int s[128];
    int t = threadIdx.x;
    int orig = (t < NB) ? g_bsum[t] : 0;
    s[t] = orig;
    __syncthreads();
    #pragma unroll
    for (int d = 1; d < 128; d <<= 1) {
        int add = (t >= d) ? s[t - d] : 0;
        __syncthreads();
        s[t] += add;
        __syncthreads();
    }
    if (t < NB) g_boff[t] = s[t] - orig;   // exclusive
}

// scan phase C: in-block exclusive scan + block offset -> rowptr/rowfill
__global__ void __launch_bounds__(1024) k_scanC() {
    __shared__ int sh[32];
    int t = threadIdx.x, lane = t & 31, wid = t >> 5;
    long long i = (long long)blockIdx.x * 1024 + t;
    int v = (i < N_NODES) ? g_cnt[i] : 0;
    int x = v;
    #pragma unroll
    for (int d = 1; d < 32; d <<= 1) {
        int tt = __shfl_up_sync(0xffffffffu, x, d);
        if (lane >= d) x += tt;
    }
    if (lane == 31) sh[wid] = x;
    __syncthreads();
    if (wid == 0) {
        int w = sh[lane];
        #pragma unroll
        for (int d = 1; d < 32; d <<= 1) {
            int tt = __shfl_up_sync(0xffffffffu, w, d);
            if (lane >= d) w += tt;
        }
        sh[lane] = w;
    }
    __syncthreads();
    if (i < N_NODES) {
        int excl = g_boff[blockIdx.x] + (wid > 0 ? sh[wid - 1] : 0) + x - v;
        g_rowptr[i]  = excl;
        g_rowfill[i] = excl;
    }
}

__global__ void __launch_bounds__(256) k_scatter(const int* __restrict__ ei32) {
    int i = blockIdx.x * blockDim.x + threadIdx.x;
    if (i < N_EDGES) {
        int s, d;
        if (g_is64) {
            s = ei32[2LL * i];
            d = ei32[2LL * N_EDGES + 2LL * i];
        } else {
            s = ei32[i];
            d = ei32[N_EDGES + i];
        }
        if ((unsigned)s < N_NODES && (unsigned)d < N_NODES) {
            int pos = atomicAdd(&g_rowfill[d], 1);
            if ((unsigned)pos < N_EDGES) {
                float w = g_dinv[s] * g_dinv[d];
                g_edges[pos] = make_int2(s, __float_as_int(w));
            }
        }
    }
}

// ---------------- GEMM1: h1 = X @ W1 (100k x 512 @ 512 x 16) ----------------
// 128 threads, 256 rows/block (2 rows/thread), K chunked by 32, f32x2 FMA.
__global__ void __launch_bounds__(128) k_gemm1(const float* __restrict__ x,
                                               const float* __restrict__ W1) {
    __shared__ float      xs[256 * 33];    // 33 stride: conflict-free
    __shared__ ulonglong2 ws2[32 * 4];     // W chunk 32x16 as f32x2 pairs
    int tid  = threadIdx.x;
    int row0 = blockIdx.x * 256;
    int rows = min(256, N_NODES - row0);
    bool v1 = tid < rows;
    bool v2 = tid + 128 < rows;

    unsigned long long acc1[8], acc2[8];
    #pragma unroll
    for (int j = 0; j < 8; j++) { acc1[j] = 0ULL; acc2[j] = 0ULL; }

    for (int c = 0; c < IN_F / 32; c++) {
        // W chunk: 32x16 floats = 128 ulonglong2 (one per thread)
        ws2[tid] = ((const ulonglong2*)(W1 + c * 32 * HID))[tid];
        // X tile: rows x 32 floats, coalesced float4 loads
        for (int idx = tid; idx < rows * 8; idx += 128) {
            int r = idx >> 3, k4 = (idx & 7) * 4;
            float4 v = *(const float4*)(x + (size_t)(row0 + r) * IN_F + c * 32 + k4);
            int b = r * 33 + k4;
            xs[b] = v.x; xs[b + 1] = v.y; xs[b + 2] = v.z; xs[b + 3] = v.w;
        }
        __syncthreads();
        int base1 = tid * 33, base2 = (tid + 128) * 33;
        #pragma unroll 4
        for (int k = 0; k < 32; k++) {
            unsigned long long xa = bcast2(v1 ? xs[base1 + k] : 0.f);
            unsigned long long xb = bcast2(v2 ? xs[base2 + k] : 0.f);
            ulonglong2 w0 = ws2[k * 4 + 0], w1 = ws2[k * 4 + 1];
            ulonglong2 w2 = ws2[k * 4 + 2], w3 = ws2[k * 4 + 3];
            acc1[0] = fma2(w0.x, xa, acc1[0]); acc1[1] = fma2(w0.y, xa, acc1[1]);
            acc1[2] = fma2(w1.x, xa, acc1[2]); acc1[3] = fma2(w1.y, xa, acc1[3]);
            acc1[4] = fma2(w2.x, xa, acc1[4]); acc1[5] = fma2(w2.y, xa, acc1[5]);
            acc1[6] = fma2(w3.x, xa, acc1[6]); acc1[7] = fma2(w3.y, xa, acc1[7]);
            acc2[0] = fma2(w0.x, xb, acc2[0]); acc2[1] = fma2(w0.y, xb, acc2[1]);
            acc2[2] = fma2(w1.x, xb, acc2[2]); acc2[3] = fma2(w1.y, xb, acc2[3]);
            acc2[4] = fma2(w2.x, xb, acc2[4]); acc2[5] = fma2(w2.y, xb, acc2[5]);
            acc2[6] = fma2(w3.x, xb, acc2[6]); acc2[7] = fma2(w3.y, xb, acc2[7]);
        }
        __syncthreads();
    }
    if (v1) {
        int r = row0 + tid;
        #pragma unroll
        for (int j = 0; j < 4; j++) {
            float2 a = unpack2(acc1[2 * j]), b = unpack2(acc1[2 * j + 1]);
            g_h1v[r * 4 + j] = make_float4(a.x, a.y, b.x, b.y);
        }
    }
    if (v2) {
        int r = row0 + tid + 128;
        #pragma unroll
        for (int j = 0; j < 4; j++) {
            float2 a = unpack2(acc2[2 * j]), b = unpack2(acc2[2 * j + 1]);
            g_h1v[r * 4 + j] = make_float4(a.x, a.y, b.x, b.y);
        }
    }
}

// ---------------- agg layer 1 + bias + relu + GEMM2 fused -------------------
__global__ void __launch_bounds__(256) k_agg1(const float* __restrict__ b1,
                                              const float* __restrict__ W2) {
    __shared__ float W2s[HID * 8];   // padded cols, col 7 = 0
    __shared__ float b1s[HID];
    int tid = threadIdx.x;
    if (tid < 128) {
        int f = tid >> 3, j = tid & 7;
        W2s[tid] = (j < NCLS) ? W2[f * NCLS + j] : 0.f;
    }
    if (tid < HID) b1s[tid] = b1[tid];
    __syncthreads();

    const float* h1 = (const float*)g_h1v;
    int warp = tid >> 5, lane = tid & 31;
    int node = blockIdx.x * 8 + warp;
    if (node >= N_NODES) return;

    int start = g_rowptr[node];
    int cnt   = g_cnt[node];
    int f = lane & 15, half = lane >> 4;

    float acc = 0.f;
    for (int e = start + half; e < start + cnt; e += 2) {
        int2 ed = g_edges[e];
        unsigned s = (unsigned)ed.x;
        if (s < N_NODES) acc += h1[(size_t)s * HID + f] * __int_as_float(ed.y);
    }
    acc += __shfl_xor_sync(0xffffffffu, acc, 16);

    float di = g_dinv[node];
    acc += h1[(size_t)node * HID + f] * di * di;
    acc = fmaxf(acc + b1s[f], 0.f);

    float hj = 0.f;
    #pragma unroll
    for (int ff = 0; ff < HID; ff++) {
        float a = __shfl_sync(0xffffffffu, acc, ff);
        hj += a * W2s[ff * 8 + (lane & 7)];
    }
    if (lane < 8) g_h2[(size_t)node * 8 + lane] = hj;
}

// ---------------- agg layer 2 + bias + log_softmax --------------------------
__global__ void __launch_bounds__(256) k_agg2(const float* __restrict__ b2,
                                              float* __restrict__ out) {
    __shared__ float b2s[8];
    int tid = threadIdx.x;
    if (tid < 8) b2s[tid] = (tid < NCLS) ? b2[tid] : 0.f;
    __syncthreads();

    int warp = tid >> 5, lane = tid & 31;
    int node = blockIdx.x * 8 + warp;
    if (node >= N_NODES) return;

    int start = g_rowptr[node];
    int cnt   = g_cnt[node];
    int j = lane & 7, q = lane >> 3;

    float acc = 0.f;
    for (int e = start + q; e < start + cnt; e += 4) {
        int2 ed = g_edges[e];
        unsigned s = (unsigned)ed.x;
        if (s < N_NODES) acc += g_h2[(size_t)s * 8 + j] * __int_as_float(ed.y);
    }
    acc += __shfl_xor_sync(0xffffffffu, acc, 16);
    acc += __shfl_xor_sync(0xffffffffu, acc, 8);

    float di = g_dinv[node];
    acc += g_h2[(size_t)node * 8 + j] * di * di + b2s[j];

    float v = (j < NCLS) ? acc : -1e30f;
    float m = v;
    m = fmaxf(m, __shfl_xor_sync(0xffffffffu, m, 4));
    m = fmaxf(m, __shfl_xor_sync(0xffffffffu, m, 2));
    m = fmaxf(m, __shfl_xor_sync(0xffffffffu, m, 1));
    float ex = (j < NCLS) ? expf(v - m) : 0.f;
    float s = ex;
    s += __shfl_xor_sync(0xffffffffu, s, 4);
    s += __shfl_xor_sync(0xffffffffu, s, 2);
    s += __shfl_xor_sync(0xffffffffu, s, 1);
    if (j < NCLS) out[(size_t)node * NCLS + j] = v - m - logf(s);
}

// ---------------- launch ----------------------------------------------------
extern "C" void kernel_launch(void* const* d_in, const int* in_sizes, int n_in,
                              void* d_out, int out_size) {
    const float* x  = nullptr;
    const int*   ei = nullptr;     // int32 view; dtype auto-detected on device
    const float* W1 = nullptr;
    const float* b1 = nullptr;
    const float* W2 = nullptr;
    const float* b2 = nullptr;

    for (int i = 0; i < n_in; i++) {
        long long sz = in_sizes[i];
        if      (sz == (long long)N_NODES * IN_F)                 x  = (const float*)d_in[i];
        else if (sz == 2LL * N_EDGES || sz == 4LL * N_EDGES)      ei = (const int*)d_in[i];
        else if (sz == (long long)IN_F * HID)                     W1 = (const float*)d_in[i];
        else if (sz == HID)                                       b1 = (const float*)d_in[i];
        else if (sz == (long long)HID * NCLS)                     W2 = (const float*)d_in[i];
        else if (sz == NCLS)                                      b2 = (const float*)d_in[i];
    }
    if (!x || !ei || !W1 || !b1 || !W2 || !b2) return;
    float* out = (float*)d_out;

    k_detect<<<1, 256>>>(ei);
    k_zero_cnt<<<(N_NODES + 255) / 256, 256>>>();
    k_hist<<<(N_EDGES + 255) / 256, 256>>>(ei);
    k_scanA<<<NB, 1024>>>();
    k_scanB<<<1, 128>>>();
    k_scanC<<<NB, 1024>>>();
    k_scatter<<<(N_EDGES + 255) / 256, 256>>>(ei);
    k_gemm1<<<(N_NODES + 255) / 256, 128>>>(x, W1);
    k_agg1<<<(N_NODES + 7) / 8, 256>>>(b1, W2);
    k_agg2<<<(N_NODES + 7) / 8, 256>>>(b2, out);
}